// round 3
// baseline (speedup 1.0000x reference)
#include <cuda_runtime.h>
#include <cuda_bf16.h>
#include <cstdint>

#define B_   64
#define T_   4096
#define IN_  32
#define H_   128
#define G_   384
#define OUT_ 32
#define BT_  (B_ * T_)

// ---------------- scratch (static __device__; allocation-free rule) ----------
__device__ float g_gi[(size_t)BT_ * G_];   // gate pre-activations (reused L0 then L1)
__device__ float g_y0[(size_t)BT_ * H_];   // layer-0 outputs

typedef unsigned long long u64t;

// ---------------- packed f32x2 helpers (sm_103a FFMA2 via PTX) ---------------
__device__ __forceinline__ u64t pk2(float a, float b) {
    u64t r; asm("mov.b64 %0, {%1,%2};" : "=l"(r) : "f"(a), "f"(b)); return r;
}
__device__ __forceinline__ u64t fma2(u64t a, u64t b, u64t c) {
    u64t d; asm("fma.rn.f32x2 %0, %1, %2, %3;" : "=l"(d) : "l"(a), "l"(b), "l"(c)); return d;
}
__device__ __forceinline__ float2 upk2(u64t a) {
    float2 f; asm("mov.b64 {%0,%1}, %2;" : "=f"(f.x), "=f"(f.y) : "l"(a)); return f;
}

__device__ __forceinline__ float sigmf(float x) {
    return __fdividef(1.f, 1.f + __expf(-x));
}
__device__ __forceinline__ float tanhfast(float x) {
    float e = __expf(-2.f * x);
    return __fdividef(1.f - e, 1.f + e);
}

// ============================================================================
// K1: gi0 = x @ W_ih0^T + b_ih0    (x: [BT,32], W: [384,32]) -> g_gi [BT,384]
// 16 bt-rows per CTA so W reads amortize; writes coalesced (thread = gate idx).
// ============================================================================
__global__ void k1_gi0(const float* __restrict__ x,
                       const float* __restrict__ W,
                       const float* __restrict__ b) {
    __shared__ float sx[16 * IN_];
    const int tid = threadIdx.x;                 // gate row 0..383
    const size_t bt0 = (size_t)blockIdx.x * 16;

    for (int i = tid; i < 16 * IN_; i += 384) sx[i] = x[bt0 * IN_ + i];

    float4 w4[8];
    const float4* wr = (const float4*)(W + (size_t)tid * IN_);
#pragma unroll
    for (int q = 0; q < 8; q++) w4[q] = __ldg(wr + q);
    const float bias = __ldg(b + tid);
    __syncthreads();

#pragma unroll 4
    for (int row = 0; row < 16; row++) {
        const float* xr = sx + row * IN_;
        float acc = bias;
#pragma unroll
        for (int q = 0; q < 8; q++) {
            acc = fmaf(w4[q].x, xr[q * 4 + 0], acc);
            acc = fmaf(w4[q].y, xr[q * 4 + 1], acc);
            acc = fmaf(w4[q].z, xr[q * 4 + 2], acc);
            acc = fmaf(w4[q].w, xr[q * 4 + 3], acc);
        }
        g_gi[(bt0 + row) * G_ + tid] = acc;
    }
}

// ============================================================================
// K3: gi1 = y0 @ W_ih1^T + b_ih1   (y0: [BT,128], W: [384,128]) -> g_gi
// Classic 64x64 tile, 256 threads, 4x4 per thread, BK=16.
// ============================================================================
__global__ void k3_gi1(const float* __restrict__ W,
                       const float* __restrict__ b) {
    __shared__ float sA[16][64];
    __shared__ float sB[16][64];
    const int tid = threadIdx.x;
    const int m0 = blockIdx.x * 64;   // bt rows
    const int n0 = blockIdx.y * 64;   // gate rows
    const int tx = tid & 15, ty = tid >> 4;
    const int lrow = tid >> 2, lk = (tid & 3) * 4;

    float acc[4][4] = {};
    for (int k0 = 0; k0 < H_; k0 += 16) {
        float4 a4 = *(const float4*)(g_y0 + (size_t)(m0 + lrow) * H_ + k0 + lk);
        float4 b4 = __ldg((const float4*)(W + (size_t)(n0 + lrow) * H_ + k0 + lk));
        sA[lk + 0][lrow] = a4.x; sA[lk + 1][lrow] = a4.y;
        sA[lk + 2][lrow] = a4.z; sA[lk + 3][lrow] = a4.w;
        sB[lk + 0][lrow] = b4.x; sB[lk + 1][lrow] = b4.y;
        sB[lk + 2][lrow] = b4.z; sB[lk + 3][lrow] = b4.w;
        __syncthreads();
#pragma unroll
        for (int kk = 0; kk < 16; kk++) {
            float4 av = *(const float4*)(&sA[kk][ty * 4]);
            float4 bv = *(const float4*)(&sB[kk][tx * 4]);
            float aa[4] = {av.x, av.y, av.z, av.w};
            float bb[4] = {bv.x, bv.y, bv.z, bv.w};
#pragma unroll
            for (int i = 0; i < 4; i++)
#pragma unroll
                for (int j = 0; j < 4; j++)
                    acc[i][j] = fmaf(aa[i], bb[j], acc[i][j]);
        }
        __syncthreads();
    }
    float4 bv = __ldg((const float4*)(b + n0 + tx * 4));
    float bb[4] = {bv.x, bv.y, bv.z, bv.w};
#pragma unroll
    for (int i = 0; i < 4; i++) {
        float4 o;
        o.x = acc[i][0] + bb[0]; o.y = acc[i][1] + bb[1];
        o.z = acc[i][2] + bb[2]; o.w = acc[i][3] + bb[3];
        *(float4*)(g_gi + (size_t)(m0 + ty * 4 + i) * G_ + n0 + tx * 4) = o;
    }
}

// ============================================================================
// K2/K4: GRU recurrence. 64 CTAs (one per batch), 384 threads (one per gate
// row). W_hh row lives in registers as 64 packed f32x2 pairs. h in SMEM,
// broadcast via LDS.128 (ulonglong2 -> pairs feed FFMA2 directly).
// gi[t+1] prefetched into a register under the matvec.
// Layer 1 additionally fuses the FC head per step (8-lane shuffle reduce).
// ============================================================================
__global__ void __launch_bounds__(384, 1) k_scan(
    const float* __restrict__ Whh, const float* __restrict__ bhh,
    const int store_y, float* __restrict__ h_final,
    const float* __restrict__ fcw, const float* __restrict__ fcb,
    float* __restrict__ out, const int do_fc)
{
    __shared__ __align__(16) float sh_h[H_];
    __shared__ float sh_r[H_], sh_z[H_], sh_n[H_];
    __shared__ __align__(16) float sfc[OUT_ * H_];
    __shared__ float sfcb[OUT_];

    const int r = threadIdx.x;       // gate row 0..383 (r:0-127, z:128-255, n:256-383)
    const int b = blockIdx.x;        // batch

    u64t wp[64];
    {
        const float4* wr = (const float4*)(Whh + (size_t)r * H_);
#pragma unroll
        for (int q = 0; q < 32; q++) {
            float4 w4 = __ldg(wr + q);
            wp[2 * q]     = pk2(w4.x, w4.y);
            wp[2 * q + 1] = pk2(w4.z, w4.w);
        }
    }
    const float bias = __ldg(bhh + r);
    if (r < H_) sh_h[r] = 0.f;
    if (do_fc) {
        for (int i = r; i < OUT_ * H_; i += 384) sfc[i] = fcw[i];
        if (r < OUT_) sfcb[r] = fcb[r];
    }
    __syncthreads();

    const float* gip = g_gi + (size_t)b * T_ * G_ + r;
    float gi_cur = __ldg(gip);

    for (int t = 0; t < T_; t++) {
        float gi_nxt = 0.f;
        if (t + 1 < T_) gi_nxt = __ldg(gip + (size_t)(t + 1) * G_);  // hidden under matvec

        // gh = W_hh[r,:] . h + b_hh[r]   (64 packed FFMA2)
        u64t a0 = 0ull, a1 = 0ull;
        const ulonglong2* h2 = (const ulonglong2*)sh_h;
#pragma unroll
        for (int q = 0; q < 32; q++) {
            ulonglong2 hp = h2[q];
            a0 = fma2(wp[2 * q],     hp.x, a0);
            a1 = fma2(wp[2 * q + 1], hp.y, a1);
        }
        float2 s0 = upk2(a0), s1 = upk2(a1);
        const float gh = (s0.x + s0.y) + (s1.x + s1.y) + bias;

        if (r < 128)      sh_r[r]       = sigmf(gi_cur + gh);
        else if (r < 256) sh_z[r - 128] = sigmf(gi_cur + gh);
        __syncthreads();

        if (r >= 256) {
            const int j = r - 256;
            sh_n[j] = tanhfast(fmaf(sh_r[j], gh, gi_cur));   // n = tanh(i_n + r*(Wh+b))
        }
        __syncthreads();

        if (r < 128) {
            const float n = sh_n[r];
            const float hnew = fmaf(sh_z[r], sh_h[r] - n, n);  // (1-z)*n + z*h
            sh_h[r] = hnew;
            if (store_y) g_y0[((size_t)b * T_ + t) * H_ + r] = hnew;
        }
        __syncthreads();

        if (do_fc && r < 256) {                               // out_t = fc_w @ h + fc_b
            const int o = r >> 3, seg = r & 7;
            const float* wrow = sfc + o * H_ + seg * 16;
            const float* hh = sh_h + seg * 16;
            float s = 0.f;
#pragma unroll
            for (int k = 0; k < 16; k++) s = fmaf(wrow[k], hh[k], s);
            s += __shfl_down_sync(0xffffffffu, s, 4, 8);
            s += __shfl_down_sync(0xffffffffu, s, 2, 8);
            s += __shfl_down_sync(0xffffffffu, s, 1, 8);
            if (seg == 0) out[((size_t)b * T_ + t) * OUT_ + o] = s + sfcb[o];
        }
        gi_cur = gi_nxt;
    }
    if (r < H_) h_final[(size_t)b * H_ + r] = sh_h[r];
}

// ============================================================================
extern "C" void kernel_launch(void* const* d_in, const int* in_sizes, int n_in,
                              void* d_out, int out_size) {
    const float* x    = (const float*)d_in[0];
    const float* Wih0 = (const float*)d_in[1];
    const float* Whh0 = (const float*)d_in[2];
    const float* bih0 = (const float*)d_in[3];
    const float* bhh0 = (const float*)d_in[4];
    const float* Wih1 = (const float*)d_in[5];
    const float* Whh1 = (const float*)d_in[6];
    const float* bih1 = (const float*)d_in[7];
    const float* bhh1 = (const float*)d_in[8];
    const float* fcw  = (const float*)d_in[9];
    const float* fcb  = (const float*)d_in[10];

    float* out  = (float*)d_out;                       // [B,T,OUT]
    float* hout = out + (size_t)B_ * T_ * OUT_;        // [2,B,H] stacked after out

    // K1: layer-0 input projection (bulk)
    k1_gi0<<<BT_ / 16, 384>>>(x, Wih0, bih0);
    // K2: layer-0 recurrence -> y0, h[0]
    k_scan<<<B_, 384>>>(Whh0, bhh0, /*store_y=*/1, hout,
                        nullptr, nullptr, nullptr, /*do_fc=*/0);
    // K3: layer-1 input projection (bulk GEMM over y0)
    k3_gi1<<<dim3(BT_ / 64, G_ / 64), 256>>>(Wih1, bih1);
    // K4: layer-1 recurrence + fused FC head -> out, h[1]
    k_scan<<<B_, 384>>>(Whh1, bhh1, /*store_y=*/0, hout + (size_t)B_ * H_,
                        fcw, fcb, out, /*do_fc=*/1);
}

// round 5
// speedup vs baseline: 1.0559x; 1.0559x over previous
#include <cuda_runtime.h>
#include <cuda_bf16.h>
#include <cstdint>

#define B_   64
#define T_   4096
#define IN_  32
#define H_   128
#define G_   384
#define OUT_ 32
#define BT_  (B_ * T_)

// ---------------- scratch (static __device__; allocation-free rule) ----------
__device__ float g_gi[(size_t)BT_ * G_];   // gate pre-activations (reused L0 then L1)
__device__ float g_y0[(size_t)BT_ * H_];   // layer-0 outputs

typedef unsigned long long u64t;

// ---------------- packed f32x2 helpers (sm_103a FFMA2 via PTX) ---------------
__device__ __forceinline__ u64t pk2(float a, float b) {
    u64t r; asm("mov.b64 %0, {%1,%2};" : "=l"(r) : "f"(a), "f"(b)); return r;
}
__device__ __forceinline__ u64t fma2(u64t a, u64t b, u64t c) {
    u64t d; asm("fma.rn.f32x2 %0, %1, %2, %3;" : "=l"(d) : "l"(a), "l"(b), "l"(c)); return d;
}
__device__ __forceinline__ u64t add2(u64t a, u64t b) {
    u64t d; asm("add.rn.f32x2 %0, %1, %2;" : "=l"(d) : "l"(a), "l"(b)); return d;
}
__device__ __forceinline__ float2 upk2(u64t a) {
    float2 f; asm("mov.b64 {%0,%1}, %2;" : "=f"(f.x), "=f"(f.y) : "l"(a)); return f;
}

__device__ __forceinline__ float sigmf(float x) {
    return __fdividef(1.f, 1.f + __expf(-x));
}
__device__ __forceinline__ float tanhfast(float x) {
    float e = __expf(-2.f * x);
    return __fdividef(1.f - e, 1.f + e);
}

// ============================================================================
// K1: gi0 = x @ W_ih0^T + b_ih0    (x: [BT,32], W: [384,32]) -> g_gi [BT,384]
// 16 bt-rows per CTA; packed FFMA2 over the K=32 dot (16 fma2/row).
// ============================================================================
__global__ void k1_gi0(const float* __restrict__ x,
                       const float* __restrict__ W,
                       const float* __restrict__ b) {
    __shared__ __align__(16) float sx[16 * IN_];
    const int tid = threadIdx.x;                 // gate row 0..383
    const size_t bt0 = (size_t)blockIdx.x * 16;

    for (int i = tid; i < 16 * IN_; i += 384) sx[i] = x[bt0 * IN_ + i];

    u64t wp[16];
    {
        const float4* wr = (const float4*)(W + (size_t)tid * IN_);
#pragma unroll
        for (int q = 0; q < 8; q++) {
            float4 w4 = __ldg(wr + q);
            wp[2 * q]     = pk2(w4.x, w4.y);
            wp[2 * q + 1] = pk2(w4.z, w4.w);
        }
    }
    const float bias = __ldg(b + tid);
    __syncthreads();

#pragma unroll 4
    for (int row = 0; row < 16; row++) {
        const ulonglong2* xr = (const ulonglong2*)(sx + row * IN_);
        u64t a0 = 0ull, a1 = 0ull;
#pragma unroll
        for (int q = 0; q < 8; q++) {
            ulonglong2 xp = xr[q];
            a0 = fma2(wp[2 * q],     xp.x, a0);
            a1 = fma2(wp[2 * q + 1], xp.y, a1);
        }
        float2 s = upk2(add2(a0, a1));
        g_gi[(bt0 + row) * G_ + tid] = s.x + s.y + bias;
    }
}

// ============================================================================
// K3: gi1 = y0 @ W_ih1^T + b_ih1   (y0: [BT,128], W: [384,128]) -> g_gi
// 64x64 tile, 256 threads, 4x4 per thread via 8 packed FFMA2, BK=16.
// ============================================================================
__global__ void k3_gi1(const float* __restrict__ W,
                       const float* __restrict__ b) {
    __shared__ float sA[16][64];
    __shared__ float sB[16][64];
    const int tid = threadIdx.x;
    const int m0 = blockIdx.x * 64;   // bt rows
    const int n0 = blockIdx.y * 64;   // gate rows
    const int tx = tid & 15, ty = tid >> 4;
    const int lrow = tid >> 2, lk = (tid & 3) * 4;

    u64t acc2[4][2] = {};
    for (int k0 = 0; k0 < H_; k0 += 16) {
        float4 a4 = *(const float4*)(g_y0 + (size_t)(m0 + lrow) * H_ + k0 + lk);
        float4 b4 = __ldg((const float4*)(W + (size_t)(n0 + lrow) * H_ + k0 + lk));
        sA[lk + 0][lrow] = a4.x; sA[lk + 1][lrow] = a4.y;
        sA[lk + 2][lrow] = a4.z; sA[lk + 3][lrow] = a4.w;
        sB[lk + 0][lrow] = b4.x; sB[lk + 1][lrow] = b4.y;
        sB[lk + 2][lrow] = b4.z; sB[lk + 3][lrow] = b4.w;
        __syncthreads();
#pragma unroll
        for (int kk = 0; kk < 16; kk++) {
            float4 av = *(const float4*)(&sA[kk][ty * 4]);
            float4 bv = *(const float4*)(&sB[kk][tx * 4]);
            u64t b01 = pk2(bv.x, bv.y), b23 = pk2(bv.z, bv.w);
            float aa[4] = {av.x, av.y, av.z, av.w};
#pragma unroll
            for (int i = 0; i < 4; i++) {
                u64t ai = pk2(aa[i], aa[i]);
                acc2[i][0] = fma2(ai, b01, acc2[i][0]);
                acc2[i][1] = fma2(ai, b23, acc2[i][1]);
            }
        }
        __syncthreads();
    }
    float4 bv = __ldg((const float4*)(b + n0 + tx * 4));
#pragma unroll
    for (int i = 0; i < 4; i++) {
        float2 p01 = upk2(acc2[i][0]), p23 = upk2(acc2[i][1]);
        float4 o;
        o.x = p01.x + bv.x; o.y = p01.y + bv.y;
        o.z = p23.x + bv.z; o.w = p23.y + bv.w;
        *(float4*)(g_gi + (size_t)(m0 + ty * 4 + i) * G_ + n0 + tx * 4) = o;
    }
}

// ============================================================================
// K2/K4: GRU recurrence. 64 CTAs (one per batch), 384 threads (one per gate
// row). W_hh row register-resident as 64 packed f32x2. h double-buffered in
// SMEM (2 barriers/step). n-threads fuse the h-update; during that phase the
// r/z threads compute the FC head for step t-1 (fully off the critical path).
// ============================================================================
__global__ void __launch_bounds__(384, 1) k_scan(
    const float* __restrict__ Whh, const float* __restrict__ bhh,
    const int store_y, float* __restrict__ h_final,
    const float* __restrict__ fcw, const float* __restrict__ fcb,
    float* __restrict__ out, const int do_fc)
{
    __shared__ __align__(16) float sh_h0[H_];
    __shared__ __align__(16) float sh_h1[H_];
    __shared__ float sh_r[H_], sh_z[H_];
    __shared__ __align__(16) float sfc[OUT_ * H_];
    __shared__ float sfcb[OUT_];

    const int r = threadIdx.x;       // gate row (r:0-127, z:128-255, n:256-383)
    const int b = blockIdx.x;        // batch

    u64t wp[64];
    {
        const float4* wr = (const float4*)(Whh + (size_t)r * H_);
#pragma unroll
        for (int q = 0; q < 16; q++) {
            float4 wA = __ldg(wr + 2 * q);
            float4 wB = __ldg(wr + 2 * q + 1);
            wp[4 * q + 0] = pk2(wA.x, wA.y);
            wp[4 * q + 1] = pk2(wA.z, wA.w);
            wp[4 * q + 2] = pk2(wB.x, wB.y);
            wp[4 * q + 3] = pk2(wB.z, wB.w);
        }
    }
    const float bias = __ldg(bhh + r);
    if (r < H_) sh_h0[r] = 0.f;
    if (do_fc) {
        for (int i = r; i < OUT_ * H_; i += 384) sfc[i] = fcw[i];
        if (r < OUT_) sfcb[r] = fcb[r];
    }
    __syncthreads();

    const float* gip = g_gi + (size_t)b * T_ * G_ + r;
    float gi_cur = __ldg(gip);

    float* hcur = sh_h0;
    float* hnxt = sh_h1;
    float* ybase = g_y0 + (size_t)b * T_ * H_ + (r - 256);     // n-threads only
    float* obase = out + (size_t)b * T_ * OUT_;

    const int o   = r >> 3;          // FC output index (r/z threads)
    const int seg = r & 7;
    const float* fcrow = sfc + o * H_ + seg * 16;

    for (int t = 0; t < T_; t++) {
        const int tn = (t + 1 < T_) ? t + 1 : t;
        const float gi_nxt = __ldg(gip + (size_t)tn * G_);     // hidden under matvec

        // ---- phase 1: gh = W_hh[r,:] . h + b ; r,z publish sigmoids --------
        u64t a0 = 0ull, a1 = 0ull, a2 = 0ull, a3 = 0ull;
        const ulonglong2* h2 = (const ulonglong2*)hcur;
#pragma unroll
        for (int q = 0; q < 16; q++) {
            ulonglong2 p0 = h2[2 * q];
            ulonglong2 p1 = h2[2 * q + 1];
            a0 = fma2(wp[4 * q + 0], p0.x, a0);
            a1 = fma2(wp[4 * q + 1], p0.y, a1);
            a2 = fma2(wp[4 * q + 2], p1.x, a2);
            a3 = fma2(wp[4 * q + 3], p1.y, a3);
        }
        float2 sf = upk2(add2(add2(a0, a1), add2(a2, a3)));
        const float gh = sf.x + sf.y + bias;

        if (r < 128)      sh_r[r]       = sigmf(gi_cur + gh);
        else if (r < 256) sh_z[r - 128] = sigmf(gi_cur + gh);
        __syncthreads();                                        // bar 1

        // ---- phase 2: n-threads update h; r/z threads do FC for t-1 --------
        if (r >= 256) {
            const int j = r - 256;
            const float nv = tanhfast(fmaf(sh_r[j], gh, gi_cur));
            const float hold = hcur[j];
            const float hnew = fmaf(sh_z[j], hold - nv, nv);    // (1-z)*n + z*h
            hnxt[j] = hnew;
            if (store_y) ybase[(size_t)t * H_] = hnew;
        } else if (do_fc && t > 0) {
            const float* hh = hcur + seg * 16;                  // h_{t-1}
            float s = 0.f;
#pragma unroll
            for (int k = 0; k < 16; k++) s = fmaf(fcrow[k], hh[k], s);
            s += __shfl_down_sync(0xffffffffu, s, 4, 8);
            s += __shfl_down_sync(0xffffffffu, s, 2, 8);
            s += __shfl_down_sync(0xffffffffu, s, 1, 8);
            if (seg == 0) obase[(size_t)(t - 1) * OUT_ + o] = s + sfcb[o];
        }
        __syncthreads();                                        // bar 2

        float* tmp = hcur; hcur = hnxt; hnxt = tmp;
        gi_cur = gi_nxt;
    }

    // final-step FC (h_{T-1} sits in hcur after the last swap)
    if (do_fc && r < 256) {
        const float* hh = hcur + seg * 16;
        float s = 0.f;
#pragma unroll
        for (int k = 0; k < 16; k++) s = fmaf(fcrow[k], hh[k], s);
        s += __shfl_down_sync(0xffffffffu, s, 4, 8);
        s += __shfl_down_sync(0xffffffffu, s, 2, 8);
        s += __shfl_down_sync(0xffffffffu, s, 1, 8);
        if (seg == 0) obase[(size_t)(T_ - 1) * OUT_ + o] = s + sfcb[o];
    }
    if (r < H_) h_final[(size_t)b * H_ + r] = hcur[r];
}

// ============================================================================
extern "C" void kernel_launch(void* const* d_in, const int* in_sizes, int n_in,
                              void* d_out, int out_size) {
    const float* x    = (const float*)d_in[0];
    const float* Wih0 = (const float*)d_in[1];
    const float* Whh0 = (const float*)d_in[2];
    const float* bih0 = (const float*)d_in[3];
    const float* bhh0 = (const float*)d_in[4];
    const float* Wih1 = (const float*)d_in[5];
    const float* Whh1 = (const float*)d_in[6];
    const float* bih1 = (const float*)d_in[7];
    const float* bhh1 = (const float*)d_in[8];
    const float* fcw  = (const float*)d_in[9];
    const float* fcb  = (const float*)d_in[10];

    float* out  = (float*)d_out;                       // [B,T,OUT]
    float* hout = out + (size_t)B_ * T_ * OUT_;        // [2,B,H] stacked after out

    // K1: layer-0 input projection (bulk)
    k1_gi0<<<BT_ / 16, 384>>>(x, Wih0, bih0);
    // K2: layer-0 recurrence -> y0, h[0]
    k_scan<<<B_, 384>>>(Whh0, bhh0, /*store_y=*/1, hout,
                        fcw, fcb, out, /*do_fc=*/0);
    // K3: layer-1 input projection (bulk GEMM over y0)
    k3_gi1<<<dim3(BT_ / 64, G_ / 64), 256>>>(Wih1, bih1);
    // K4: layer-1 recurrence + fused FC head -> out, h[1]
    k_scan<<<B_, 384>>>(Whh1, bhh1, /*store_y=*/0, hout + (size_t)B_ * H_,
                        fcw, fcb, out, /*do_fc=*/1);
}